// round 4
// baseline (speedup 1.0000x reference)
#include <cuda_runtime.h>

// gRNN over 1024 complete binary trees, depth 10, hidden SIZE=100.
// Levels 8..5: packed-f32x2 register-blocked GEMM kernels (leaf fused at level 8).
// Levels 4..0 + output projection: one fused per-tree kernel.

#define S        100
#define OP       102     // Ww_s row stride, k-major [k][o], even for LDS.64 pairs
#define TM       128     // node rows per CTA (main kernel)
#define TMP      132     // comb_s row stride, k-major [k][r], mult of 4 for LDS.128
#define NTH      160     // 16 row-groups x 10 col-groups, micro-tile 8x10
#define NTREES   1024
#define NNODES   1023

typedef unsigned long long u64;

// Ping-pong level buffers (no runtime allocation allowed).
__device__ float g_bufA[NTREES * 256 * S];   // levels 8, 6
__device__ float g_bufB[NTREES * 128 * S];   // levels 7, 5

__device__ __forceinline__ u64 pack2(float x, float y) {
    u64 r; asm("mov.b64 %0, {%1,%2};" : "=l"(r) : "f"(x), "f"(y)); return r;
}
__device__ __forceinline__ void unpack2(u64 v, float& x, float& y) {
    asm("mov.b64 {%0,%1}, %2;" : "=f"(x), "=f"(y) : "l"(v));
}
__device__ __forceinline__ u64 fma2(u64 a, u64 b, u64 c) {
    u64 d; asm("fma.rn.f32x2 %0, %1, %2, %3;" : "=l"(d) : "l"(a), "l"(b), "l"(c));
    return d;
}

#define MAIN_SMEM ((S*OP + S*TMP + 3*S) * (int)sizeof(float))
#define TREE_SMEM ((S*OP + 2*S*34 + 3*S) * (int)sizeof(float))

// ---------------------------------------------------------------------------
// Main level kernel: computes h for TM nodes of level d.
// comb_s is stored k-major; Ww_s is stored k-major (transposed from gmem).
// ---------------------------------------------------------------------------
template<bool LEAF>
__global__ __launch_bounds__(NTH)
void level_kernel(const float* __restrict__ times,
                  const float* __restrict__ Qw,
                  const float* __restrict__ Qb,
                  const float* __restrict__ Ww,
                  const float* __restrict__ Wb,
                  const float* __restrict__ prev,
                  float* __restrict__ cur,
                  int d)
{
    extern __shared__ float sm[];
    float* Ww_s   = sm;                 // [S][OP]   Ww_s[k*OP + o]
    float* comb_s = Ww_s + S * OP;      // [S][TMP]  comb_s[k*TMP + r]
    float* Qw_s   = comb_s + S * TMP;   // [S]
    float* Qb_s   = Qw_s + S;
    float* Wb_s   = Qb_s + S;

    const int tid     = threadIdx.x;
    const int lvl     = 1 << d;
    const int baseRow = blockIdx.x * TM;

    // ---- stage weights (transpose Ww to k-major) ----
    for (int idx = tid; idx < S; idx += NTH) {
        Qw_s[idx] = Qw[idx];
        Qb_s[idx] = Qb[idx];
        Wb_s[idx] = Wb[idx];
    }
    for (int idx = tid; idx < S * S; idx += NTH) {
        int o = idx / S, k = idx % S;
        Ww_s[k * OP + o] = Ww[idx];        // coalesced read, 2-way STS
    }
    __syncthreads();   // Qw_s/Qb_s ready for LEAF build

    // ---- build comb tile, k-major: comb_s[k][r] = h_left + h_right ----
    if (LEAF) {
        for (int idx = tid; idx < TM * S; idx += NTH) {
            int r = idx / S, k = idx % S;
            int g = baseRow + r;
            int b = g >> d;
            int n = g & (lvl - 1);
            const float* tb = times + (long)b * NNODES;
            float tL = tb[2 * lvl - 1 + 2 * n];
            float tR = tb[2 * lvl + 2 * n];
            float qw = Qw_s[k], qb = Qb_s[k];
            comb_s[k * TMP + r] = fmaxf(fmaf(tL, qw, qb), 0.f)
                                + fmaxf(fmaf(tR, qw, qb), 0.f);
        }
    } else {
        for (int idx = tid; idx < TM * S; idx += NTH) {
            int r = idx / S, k = idx % S;
            long g = baseRow + r;
            comb_s[k * TMP + r] = prev[(2 * g) * S + k] + prev[(2 * g + 1) * S + k];
        }
    }
    __syncthreads();

    // ---- packed-f32x2 GEMM: 8 nodes x 10 outputs per thread ----
    const int i  = tid & 15;       // row group 0..15
    const int j  = tid >> 4;       // col group 0..9
    const int r0 = i * 8;
    const int c0 = j * 10;

    u64 acc[8][5];
#pragma unroll
    for (int r = 0; r < 8; r++)
#pragma unroll
        for (int c = 0; c < 5; c++) acc[r][c] = 0ull;

#pragma unroll 2
    for (int k = 0; k < S; k++) {
        const float4 a03 = *(const float4*)&comb_s[k * TMP + r0];
        const float4 a47 = *(const float4*)&comb_s[k * TMP + r0 + 4];
        u64 A[8];
        A[0] = pack2(a03.x, a03.x); A[1] = pack2(a03.y, a03.y);
        A[2] = pack2(a03.z, a03.z); A[3] = pack2(a03.w, a03.w);
        A[4] = pack2(a47.x, a47.x); A[5] = pack2(a47.y, a47.y);
        A[6] = pack2(a47.z, a47.z); A[7] = pack2(a47.w, a47.w);
        const u64* wrow = (const u64*)&Ww_s[k * OP + c0];
#pragma unroll
        for (int c = 0; c < 5; c++) {
            u64 B = wrow[c];
#pragma unroll
            for (int r = 0; r < 8; r++)
                acc[r][c] = fma2(A[r], B, acc[r][c]);
        }
    }

    // ---- epilogue: + Wb + t*Qw + Qb, relu, store ----
#pragma unroll
    for (int r = 0; r < 8; r++) {
        int g = baseRow + r0 + r;
        int b = g >> d;
        int n = g & (lvl - 1);
        float t = times[(long)b * NNODES + (lvl - 1) + n];
        float* crow = cur + (long)g * S + c0;
#pragma unroll
        for (int c = 0; c < 5; c++) {
            float v0, v1;
            unpack2(acc[r][c], v0, v1);
            int o = c0 + 2 * c;
            float h0 = fmaxf(v0 + Wb_s[o]     + fmaf(t, Qw_s[o],     Qb_s[o]),     0.f);
            float h1 = fmaxf(v1 + Wb_s[o + 1] + fmaf(t, Qw_s[o + 1], Qb_s[o + 1]), 0.f);
            *(float2*)(crow + 2 * c) = make_float2(h0, h1);
        }
    }
}

// ---------------------------------------------------------------------------
// Tree tail kernel: one CTA per tree, levels 4..0 + output projection.
// h buffers stored k-major [o][node] with stride 34 so children pairs are a
// single LDS.64.
// ---------------------------------------------------------------------------
__global__ __launch_bounds__(NTH)
void tree_kernel(const float* __restrict__ times,
                 const float* __restrict__ Qw,
                 const float* __restrict__ Qb,
                 const float* __restrict__ Ww,
                 const float* __restrict__ Wb,
                 const float* __restrict__ Pw,
                 const float* __restrict__ Pb,
                 const float* __restrict__ prev,   // level-5 h: [tree*32 + n][S]
                 float* __restrict__ out)
{
    extern __shared__ float sm[];
    float* Ww_s = sm;                  // [S][OP]
    float* hA   = Ww_s + S * OP;       // [S][34]
    float* hB   = hA + S * 34;         // [S][34]
    float* Qw_s = hB + S * 34;
    float* Qb_s = Qw_s + S;
    float* Wb_s = Qb_s + S;

    const int tid  = threadIdx.x;
    const int tree = blockIdx.x;
    const float* tb = times + (long)tree * NNODES;

    for (int idx = tid; idx < S; idx += NTH) {
        Qw_s[idx] = Qw[idx];
        Qb_s[idx] = Qb[idx];
        Wb_s[idx] = Wb[idx];
    }
    for (int idx = tid; idx < S * S; idx += NTH) {
        int o = idx / S, k = idx % S;
        Ww_s[k * OP + o] = Ww[idx];
    }
    // load level-5 h (32 nodes) transposed into hA
    const float* p5 = prev + (long)tree * 32 * S;
    for (int idx = tid; idx < 32 * S; idx += NTH) {
        int r = idx / S, k = idx % S;
        hA[k * 34 + r] = p5[r * S + k];
    }
    __syncthreads();

    const int rg = tid / 10;       // row (node) index, 0..15
    const int cg = tid % 10;       // col group
    const int c0 = cg * 10;

    float* hin  = hA;
    float* hout = hB;

    for (int d = 4; d >= 0; d--) {
        int M = 1 << d;
        if (rg < M) {
            u64 acc[5] = {0, 0, 0, 0, 0};
#pragma unroll 2
            for (int k = 0; k < S; k++) {
                float2 hp = *(const float2*)&hin[k * 34 + 2 * rg];
                float a = hp.x + hp.y;
                u64 A = pack2(a, a);
                const u64* wrow = (const u64*)&Ww_s[k * OP + c0];
#pragma unroll
                for (int c = 0; c < 5; c++)
                    acc[c] = fma2(A, wrow[c], acc[c]);
            }
            float t = tb[M - 1 + rg];
#pragma unroll
            for (int c = 0; c < 5; c++) {
                float v0, v1;
                unpack2(acc[c], v0, v1);
                int o = c0 + 2 * c;
                hout[o * 34 + rg]       = fmaxf(v0 + Wb_s[o]     + fmaf(t, Qw_s[o],     Qb_s[o]),     0.f);
                hout[(o + 1) * 34 + rg] = fmaxf(v1 + Wb_s[o + 1] + fmaf(t, Qw_s[o + 1], Qb_s[o + 1]), 0.f);
            }
        }
        __syncthreads();
        float* tmp = hin; hin = hout; hout = tmp;
    }

    // root h is in hin[o*34 + 0]; project to 5 params.
    // warp p (0..4) computes param p via lane-strided dot + shfl reduce.
    int p    = tid >> 5;
    int lane = tid & 31;
    float s = 0.f;
    for (int o = lane; o < S; o += 32)
        s = fmaf(hin[o * 34], Pw[p * S + o], s);
#pragma unroll
    for (int off = 16; off; off >>= 1)
        s += __shfl_down_sync(0xffffffffu, s, off);
    if (lane == 0)
        out[tree * 5 + p] = s + Pb[p];
}

// ---------------------------------------------------------------------------
extern "C" void kernel_launch(void* const* d_in, const int* in_sizes, int n_in,
                              void* d_out, int out_size)
{
    const float* times = (const float*)d_in[0];
    const float* Qw    = (const float*)d_in[1];
    const float* Qb    = (const float*)d_in[2];
    const float* Ww    = (const float*)d_in[3];
    const float* Wb    = (const float*)d_in[4];
    const float* Pw    = (const float*)d_in[5];
    const float* Pb    = (const float*)d_in[6];
    float* out = (float*)d_out;

    float *pA = nullptr, *pB = nullptr;
    cudaGetSymbolAddress((void**)&pA, g_bufA);
    cudaGetSymbolAddress((void**)&pB, g_bufB);

    cudaFuncSetAttribute(level_kernel<true>,
                         cudaFuncAttributeMaxDynamicSharedMemorySize, MAIN_SMEM);
    cudaFuncSetAttribute(level_kernel<false>,
                         cudaFuncAttributeMaxDynamicSharedMemorySize, MAIN_SMEM);
    cudaFuncSetAttribute(tree_kernel,
                         cudaFuncAttributeMaxDynamicSharedMemorySize, TREE_SMEM);

    // Level 8 (leaves fused) -> A
    level_kernel<true><<<(NTREES * 256) / TM, NTH, MAIN_SMEM>>>(
        times, Qw, Qb, Ww, Wb, nullptr, pA, 8);
    // Level 7: A -> B
    level_kernel<false><<<(NTREES * 128) / TM, NTH, MAIN_SMEM>>>(
        times, Qw, Qb, Ww, Wb, pA, pB, 7);
    // Level 6: B -> A
    level_kernel<false><<<(NTREES * 64) / TM, NTH, MAIN_SMEM>>>(
        times, Qw, Qb, Ww, Wb, pB, pA, 6);
    // Level 5: A -> B
    level_kernel<false><<<(NTREES * 32) / TM, NTH, MAIN_SMEM>>>(
        times, Qw, Qb, Ww, Wb, pA, pB, 5);

    // Levels 4..0 + projection: one CTA per tree
    tree_kernel<<<NTREES, NTH, TREE_SMEM>>>(
        times, Qw, Qb, Ww, Wb, Pw, Pb, pB, out);
}

// round 5
// speedup vs baseline: 1.2130x; 1.2130x over previous
#include <cuda_runtime.h>

// gRNN over 1024 complete binary trees, depth 10, hidden SIZE=100.
// Levels 8..5: packed-f32x2 GEMM, 320 threads, micro-tile 4x10, 2 CTA/SM.
// Levels 4..0 + output projection: one fused per-tree kernel.

#define S        100
#define OP       102     // Ww_s row stride, k-major [k][o]
#define TM       128     // node rows per CTA
#define TMP      132     // comb_s row stride, k-major [k][r]
#define NTH      320     // 32 row-groups (lanes) x 10 col-groups (warps)
#define NTREES   1024
#define NNODES   1023

typedef unsigned long long u64;

__device__ float g_bufA[NTREES * 256 * S];   // levels 8, 6
__device__ float g_bufB[NTREES * 128 * S];   // levels 7, 5

__device__ __forceinline__ u64 pack2(float x, float y) {
    u64 r; asm("mov.b64 %0, {%1,%2};" : "=l"(r) : "f"(x), "f"(y)); return r;
}
__device__ __forceinline__ void unpack2(u64 v, float& x, float& y) {
    asm("mov.b64 {%0,%1}, %2;" : "=f"(x), "=f"(y) : "l"(v));
}
__device__ __forceinline__ u64 fma2(u64 a, u64 b, u64 c) {
    u64 d; asm("fma.rn.f32x2 %0, %1, %2, %3;" : "=l"(d) : "l"(a), "l"(b), "l"(c));
    return d;
}

#define MAIN_SMEM ((S*OP + S*TMP + 3*S) * (int)sizeof(float))
#define TREE_SMEM ((S*OP + 2*S*34 + 3*S) * (int)sizeof(float))

// ---------------------------------------------------------------------------
// Main level kernel: TM nodes of level d.
// comb_s k-major [k][r]; Ww_s k-major [k][o].
// lane (tid&31) -> 4 rows; warp (tid>>5, 0..9) -> 10 cols (warp-uniform B).
// ---------------------------------------------------------------------------
template<bool LEAF>
__global__ __launch_bounds__(NTH, 2)
void level_kernel(const float* __restrict__ times,
                  const float* __restrict__ Qw,
                  const float* __restrict__ Qb,
                  const float* __restrict__ Ww,
                  const float* __restrict__ Wb,
                  const float* __restrict__ prev,
                  float* __restrict__ cur,
                  int d)
{
    extern __shared__ float sm[];
    float* Ww_s   = sm;                 // [S][OP]
    float* comb_s = Ww_s + S * OP;      // [S][TMP]
    float* Qw_s   = comb_s + S * TMP;
    float* Qb_s   = Qw_s + S;
    float* Wb_s   = Qb_s + S;

    const int tid     = threadIdx.x;
    const int lvl     = 1 << d;
    const int baseRow = blockIdx.x * TM;

    // ---- stage weights (Ww transposed to k-major) ----
    for (int idx = tid; idx < S; idx += NTH) {
        Qw_s[idx] = Qw[idx];
        Qb_s[idx] = Qb[idx];
        Wb_s[idx] = Wb[idx];
    }
    for (int idx = tid; idx < S * S; idx += NTH) {
        int o = idx / S, k = idx % S;
        Ww_s[k * OP + o] = Ww[idx];
    }
    __syncthreads();

    // ---- build comb tile k-major: comb_s[k][r] = h_left + h_right ----
    if (LEAF) {
        for (int idx = tid; idx < TM * S; idx += NTH) {
            int r = idx / S, k = idx % S;
            int g = baseRow + r;
            int b = g >> d;
            int n = g & (lvl - 1);
            const float* tb = times + (long)b * NNODES;
            float tL = tb[2 * lvl - 1 + 2 * n];
            float tR = tb[2 * lvl + 2 * n];
            float qw = Qw_s[k], qb = Qb_s[k];
            comb_s[k * TMP + r] = fmaxf(fmaf(tL, qw, qb), 0.f)
                                + fmaxf(fmaf(tR, qw, qb), 0.f);
        }
    } else {
        // float4 over k: 25 vec4 per row
        for (int idx = tid; idx < TM * (S / 4); idx += NTH) {
            int r = idx / (S / 4), k4 = idx % (S / 4);
            long g = baseRow + r;
            float4 L = *(const float4*)&prev[(2 * g) * S + 4 * k4];
            float4 R = *(const float4*)&prev[(2 * g + 1) * S + 4 * k4];
            int kb = 4 * k4;
            comb_s[(kb + 0) * TMP + r] = L.x + R.x;
            comb_s[(kb + 1) * TMP + r] = L.y + R.y;
            comb_s[(kb + 2) * TMP + r] = L.z + R.z;
            comb_s[(kb + 3) * TMP + r] = L.w + R.w;
        }
    }
    __syncthreads();

    // ---- packed-f32x2 GEMM: 4 rows x 10 cols per thread ----
    const int lane = tid & 31;
    const int warp = tid >> 5;
    const int r0 = lane * 4;
    const int c0 = warp * 10;

    u64 acc[4][5];
#pragma unroll
    for (int r = 0; r < 4; r++)
#pragma unroll
        for (int c = 0; c < 5; c++) acc[r][c] = 0ull;

#pragma unroll 2
    for (int k = 0; k < S; k++) {
        const float4 a4 = *(const float4*)&comb_s[k * TMP + r0];
        u64 A[4];
        A[0] = pack2(a4.x, a4.x);
        A[1] = pack2(a4.y, a4.y);
        A[2] = pack2(a4.z, a4.z);
        A[3] = pack2(a4.w, a4.w);
        const u64* wrow = (const u64*)&Ww_s[k * OP + c0];   // warp-uniform
#pragma unroll
        for (int c = 0; c < 5; c++) {
            u64 B = wrow[c];
#pragma unroll
            for (int r = 0; r < 4; r++)
                acc[r][c] = fma2(A[r], B, acc[r][c]);
        }
    }

    // ---- epilogue: + Wb + t*Qw + Qb, relu, store ----
#pragma unroll
    for (int r = 0; r < 4; r++) {
        int g = baseRow + r0 + r;
        int b = g >> d;
        int n = g & (lvl - 1);
        float t = times[(long)b * NNODES + (lvl - 1) + n];
        float* crow = cur + (long)g * S + c0;
#pragma unroll
        for (int c = 0; c < 5; c++) {
            float v0, v1;
            unpack2(acc[r][c], v0, v1);
            int o = c0 + 2 * c;
            float h0 = fmaxf(v0 + Wb_s[o]     + fmaf(t, Qw_s[o],     Qb_s[o]),     0.f);
            float h1 = fmaxf(v1 + Wb_s[o + 1] + fmaf(t, Qw_s[o + 1], Qb_s[o + 1]), 0.f);
            *(float2*)(crow + 2 * c) = make_float2(h0, h1);
        }
    }
}

// ---------------------------------------------------------------------------
// Tree tail: one CTA per tree, levels 4..0 + projection. (unchanged)
// ---------------------------------------------------------------------------
__global__ __launch_bounds__(160)
void tree_kernel(const float* __restrict__ times,
                 const float* __restrict__ Qw,
                 const float* __restrict__ Qb,
                 const float* __restrict__ Ww,
                 const float* __restrict__ Wb,
                 const float* __restrict__ Pw,
                 const float* __restrict__ Pb,
                 const float* __restrict__ prev,   // level-5 h
                 float* __restrict__ out)
{
    extern __shared__ float sm[];
    float* Ww_s = sm;                  // [S][OP]
    float* hA   = Ww_s + S * OP;       // [S][34]
    float* hB   = hA + S * 34;         // [S][34]
    float* Qw_s = hB + S * 34;
    float* Qb_s = Qw_s + S;
    float* Wb_s = Qb_s + S;

    const int tid  = threadIdx.x;
    const int tree = blockIdx.x;
    const float* tb = times + (long)tree * NNODES;

    for (int idx = tid; idx < S; idx += 160) {
        Qw_s[idx] = Qw[idx];
        Qb_s[idx] = Qb[idx];
        Wb_s[idx] = Wb[idx];
    }
    for (int idx = tid; idx < S * S; idx += 160) {
        int o = idx / S, k = idx % S;
        Ww_s[k * OP + o] = Ww[idx];
    }
    const float* p5 = prev + (long)tree * 32 * S;
    for (int idx = tid; idx < 32 * S; idx += 160) {
        int r = idx / S, k = idx % S;
        hA[k * 34 + r] = p5[r * S + k];
    }
    __syncthreads();

    const int rg = tid / 10;
    const int cg = tid % 10;
    const int c0 = cg * 10;

    float* hin  = hA;
    float* hout = hB;

    for (int d = 4; d >= 0; d--) {
        int M = 1 << d;
        if (rg < M) {
            u64 acc[5] = {0, 0, 0, 0, 0};
#pragma unroll 2
            for (int k = 0; k < S; k++) {
                float2 hp = *(const float2*)&hin[k * 34 + 2 * rg];
                float a = hp.x + hp.y;
                u64 A = pack2(a, a);
                const u64* wrow = (const u64*)&Ww_s[k * OP + c0];
#pragma unroll
                for (int c = 0; c < 5; c++)
                    acc[c] = fma2(A, wrow[c], acc[c]);
            }
            float t = tb[M - 1 + rg];
#pragma unroll
            for (int c = 0; c < 5; c++) {
                float v0, v1;
                unpack2(acc[c], v0, v1);
                int o = c0 + 2 * c;
                hout[o * 34 + rg]       = fmaxf(v0 + Wb_s[o]     + fmaf(t, Qw_s[o],     Qb_s[o]),     0.f);
                hout[(o + 1) * 34 + rg] = fmaxf(v1 + Wb_s[o + 1] + fmaf(t, Qw_s[o + 1], Qb_s[o + 1]), 0.f);
            }
        }
        __syncthreads();
        float* tmp = hin; hin = hout; hout = tmp;
    }

    int p    = tid >> 5;
    int lane = tid & 31;
    float s = 0.f;
    for (int o = lane; o < S; o += 32)
        s = fmaf(hin[o * 34], Pw[p * S + o], s);
#pragma unroll
    for (int off = 16; off; off >>= 1)
        s += __shfl_down_sync(0xffffffffu, s, off);
    if (lane == 0)
        out[tree * 5 + p] = s + Pb[p];
}

// ---------------------------------------------------------------------------
extern "C" void kernel_launch(void* const* d_in, const int* in_sizes, int n_in,
                              void* d_out, int out_size)
{
    const float* times = (const float*)d_in[0];
    const float* Qw    = (const float*)d_in[1];
    const float* Qb    = (const float*)d_in[2];
    const float* Ww    = (const float*)d_in[3];
    const float* Wb    = (const float*)d_in[4];
    const float* Pw    = (const float*)d_in[5];
    const float* Pb    = (const float*)d_in[6];
    float* out = (float*)d_out;

    float *pA = nullptr, *pB = nullptr;
    cudaGetSymbolAddress((void**)&pA, g_bufA);
    cudaGetSymbolAddress((void**)&pB, g_bufB);

    cudaFuncSetAttribute(level_kernel<true>,
                         cudaFuncAttributeMaxDynamicSharedMemorySize, MAIN_SMEM);
    cudaFuncSetAttribute(level_kernel<false>,
                         cudaFuncAttributeMaxDynamicSharedMemorySize, MAIN_SMEM);
    cudaFuncSetAttribute(tree_kernel,
                         cudaFuncAttributeMaxDynamicSharedMemorySize, TREE_SMEM);

    // Level 8 (leaves fused) -> A
    level_kernel<true><<<(NTREES * 256) / TM, NTH, MAIN_SMEM>>>(
        times, Qw, Qb, Ww, Wb, nullptr, pA, 8);
    // Level 7: A -> B
    level_kernel<false><<<(NTREES * 128) / TM, NTH, MAIN_SMEM>>>(
        times, Qw, Qb, Ww, Wb, pA, pB, 7);
    // Level 6: B -> A
    level_kernel<false><<<(NTREES * 64) / TM, NTH, MAIN_SMEM>>>(
        times, Qw, Qb, Ww, Wb, pB, pA, 6);
    // Level 5: A -> B
    level_kernel<false><<<(NTREES * 32) / TM, NTH, MAIN_SMEM>>>(
        times, Qw, Qb, Ww, Wb, pA, pB, 5);

    // Levels 4..0 + projection
    tree_kernel<<<NTREES, 160, TREE_SMEM>>>(
        times, Qw, Qb, Ww, Wb, Pw, Pb, pB, out);
}

// round 9
// speedup vs baseline: 1.4297x; 1.1786x over previous
#include <cuda_runtime.h>

// gRNN over 1024 complete binary trees, depth 10, hidden SIZE=100.
// h is stored K-MAJOR in gmem between levels: h[o][node], node fastest.
// Levels 8..5: packed-f32x2 GEMM, 320 thr, micro-tile 4x10, split-K staging,
//              3 CTAs/SM. Levels 4..0 + projection: one fused per-tree kernel.

#define S        100
#define OP       100     // Ww_s row stride, k-major [k][o]
#define TM       128     // node rows per CTA
#define TMP      132     // comb_s row stride, k-major [kk][r]
#define KH       50      // k-half size (split-K staging)
#define NTH      320
#define NTREES   1024
#define NNODES   1023

typedef unsigned long long u64;

// Ping-pong level buffers, k-major: buf[o * M + node].
__device__ float g_bufA[NTREES * 256 * S];   // levels 8, 6
__device__ float g_bufB[NTREES * 128 * S];   // levels 7, 5

__device__ __forceinline__ u64 pack2(float x, float y) {
    u64 r; asm("mov.b64 %0, {%1,%2};" : "=l"(r) : "f"(x), "f"(y)); return r;
}
__device__ __forceinline__ void unpack2(u64 v, float& x, float& y) {
    asm("mov.b64 {%0,%1}, %2;" : "=f"(x), "=f"(y) : "l"(v));
}
__device__ __forceinline__ u64 fma2(u64 a, u64 b, u64 c) {
    u64 d; asm("fma.rn.f32x2 %0, %1, %2, %3;" : "=l"(d) : "l"(a), "l"(b), "l"(c));
    return d;
}

#define MAIN_SMEM ((S*OP + KH*TMP + 3*S) * (int)sizeof(float))
#define TREE_SMEM ((S*102 + 2*S*34 + 3*S) * (int)sizeof(float))

// ---------------------------------------------------------------------------
// Level kernel. prev/cur are k-major. lane -> 4 rows, warp -> 10 cols.
// ---------------------------------------------------------------------------
template<bool LEAF>
__global__ __launch_bounds__(NTH, 3)
void level_kernel(const float* __restrict__ times,
                  const float* __restrict__ Qw,
                  const float* __restrict__ Qb,
                  const float* __restrict__ Ww,
                  const float* __restrict__ Wb,
                  const float* __restrict__ prev,
                  float* __restrict__ cur,
                  int d)
{
    extern __shared__ float sm[];
    float* Ww_s   = sm;                 // [S][OP]  k-major
    float* comb_s = Ww_s + S * OP;      // [KH][TMP]
    float* Qw_s   = comb_s + KH * TMP;
    float* Qb_s   = Qw_s + S;
    float* Wb_s   = Qb_s + S;

    const int  tid     = threadIdx.x;
    const int  lvl     = 1 << d;
    const int  M       = NTREES << d;       // rows this level
    const long Mprev   = (long)M * 2;
    const int  baseRow = blockIdx.x * TM;

    for (int idx = tid; idx < S; idx += NTH) {
        Qw_s[idx] = Qw[idx];
        Qb_s[idx] = Qb[idx];
        Wb_s[idx] = Wb[idx];
    }
    for (int idx = tid; idx < S * S; idx += NTH) {
        int o = idx / S, k = idx % S;
        Ww_s[k * OP + o] = Ww[idx];
    }

    const int lane = tid & 31;
    const int warp = tid >> 5;
    const int r0 = lane * 4;
    const int c0 = warp * 10;

    u64 acc[4][5];
#pragma unroll
    for (int r = 0; r < 4; r++)
#pragma unroll
        for (int c = 0; c < 5; c++) acc[r][c] = 0ull;

    __syncthreads();   // Ww_s / Qw_s ready

#pragma unroll 1
    for (int half = 0; half < 2; half++) {
        const int k0 = half * KH;

        // ---- build comb half: comb_s[kk][r] = h_left + h_right ----
        if (LEAF) {
            for (int idx = tid; idx < KH * TM; idx += NTH) {
                int kk = idx / TM, r = idx % TM;   // consecutive tid -> consecutive r
                int k = k0 + kk;
                int g = baseRow + r;
                int b = g >> d;
                int n = g & (lvl - 1);
                const float* tb = times + (long)b * NNODES;
                float tL = tb[2 * lvl - 1 + 2 * n];
                float tR = tb[2 * lvl + 2 * n];
                float qw = Qw_s[k], qb = Qb_s[k];
                comb_s[kk * TMP + r] = fmaxf(fmaf(tL, qw, qb), 0.f)
                                     + fmaxf(fmaf(tR, qw, qb), 0.f);
            }
        } else {
            // 8 rows per iteration: 16 consecutive child floats -> 8 sums
            for (int idx = tid; idx < KH * (TM / 8); idx += NTH) {
                int kk = idx / (TM / 8), r8 = idx % (TM / 8);
                const float* p = prev + (long)(k0 + kk) * Mprev
                                      + 2 * (long)(baseRow + 8 * r8);
                float4 v0 = *(const float4*)(p + 0);
                float4 v1 = *(const float4*)(p + 4);
                float4 v2 = *(const float4*)(p + 8);
                float4 v3 = *(const float4*)(p + 12);
                float* cs = &comb_s[kk * TMP + 8 * r8];
                *(float4*)(cs + 0) = make_float4(v0.x + v0.y, v0.z + v0.w,
                                                 v1.x + v1.y, v1.z + v1.w);
                *(float4*)(cs + 4) = make_float4(v2.x + v2.y, v2.z + v2.w,
                                                 v3.x + v3.y, v3.z + v3.w);
            }
        }
        __syncthreads();

        // ---- packed-f32x2 GEMM over this k-half ----
#pragma unroll 2
        for (int kk = 0; kk < KH; kk++) {
            const float4 a4 = *(const float4*)&comb_s[kk * TMP + r0];
            u64 A0 = pack2(a4.x, a4.x);
            u64 A1 = pack2(a4.y, a4.y);
            u64 A2 = pack2(a4.z, a4.z);
            u64 A3 = pack2(a4.w, a4.w);
            const u64* wrow = (const u64*)&Ww_s[(k0 + kk) * OP + c0]; // warp-uniform
#pragma unroll
            for (int c = 0; c < 5; c++) {
                u64 B = wrow[c];
                acc[0][c] = fma2(A0, B, acc[0][c]);
                acc[1][c] = fma2(A1, B, acc[1][c]);
                acc[2][c] = fma2(A2, B, acc[2][c]);
                acc[3][c] = fma2(A3, B, acc[3][c]);
            }
        }
        __syncthreads();   // before rebuilding comb_s
    }

    // ---- epilogue: + Wb + t*Qw + Qb, relu; k-major coalesced stores ----
    float tv[4];
#pragma unroll
    for (int r = 0; r < 4; r++) {
        int g = baseRow + r0 + r;
        int b = g >> d;
        int n = g & (lvl - 1);
        tv[r] = times[(long)b * NNODES + (lvl - 1) + n];
    }
#pragma unroll
    for (int c = 0; c < 5; c++) {
        int o0 = c0 + 2 * c;
        float x0, y0, x1, y1, x2, y2, x3, y3;
        unpack2(acc[0][c], x0, y0);
        unpack2(acc[1][c], x1, y1);
        unpack2(acc[2][c], x2, y2);
        unpack2(acc[3][c], x3, y3);
        float4 lo, hi;
        lo.x = fmaxf(x0 + Wb_s[o0]   + fmaf(tv[0], Qw_s[o0],   Qb_s[o0]),   0.f);
        lo.y = fmaxf(x1 + Wb_s[o0]   + fmaf(tv[1], Qw_s[o0],   Qb_s[o0]),   0.f);
        lo.z = fmaxf(x2 + Wb_s[o0]   + fmaf(tv[2], Qw_s[o0],   Qb_s[o0]),   0.f);
        lo.w = fmaxf(x3 + Wb_s[o0]   + fmaf(tv[3], Qw_s[o0],   Qb_s[o0]),   0.f);
        hi.x = fmaxf(y0 + Wb_s[o0+1] + fmaf(tv[0], Qw_s[o0+1], Qb_s[o0+1]), 0.f);
        hi.y = fmaxf(y1 + Wb_s[o0+1] + fmaf(tv[1], Qw_s[o0+1], Qb_s[o0+1]), 0.f);
        hi.z = fmaxf(y2 + Wb_s[o0+1] + fmaf(tv[2], Qw_s[o0+1], Qb_s[o0+1]), 0.f);
        hi.w = fmaxf(y3 + Wb_s[o0+1] + fmaf(tv[3], Qw_s[o0+1], Qb_s[o0+1]), 0.f);
        long g0 = baseRow + r0;
        *(float4*)&cur[(long)o0 * M + g0]       = lo;
        *(float4*)&cur[(long)(o0 + 1) * M + g0] = hi;
    }
}

// ---------------------------------------------------------------------------
// Tree tail: one CTA per tree, levels 4..0 + projection. prev is k-major.
// ---------------------------------------------------------------------------
__global__ __launch_bounds__(160)
void tree_kernel(const float* __restrict__ times,
                 const float* __restrict__ Qw,
                 const float* __restrict__ Qb,
                 const float* __restrict__ Ww,
                 const float* __restrict__ Wb,
                 const float* __restrict__ Pw,
                 const float* __restrict__ Pb,
                 const float* __restrict__ prev,   // level-5 h, k-major [k][32768]
                 float* __restrict__ out)
{
    extern __shared__ float sm[];
    float* Ww_s = sm;                  // [S][102]
    float* hA   = Ww_s + S * 102;      // [S][34]
    float* hB   = hA + S * 34;
    float* Qw_s = hB + S * 34;
    float* Qb_s = Qw_s + S;
    float* Wb_s = Qb_s + S;

    const int tid  = threadIdx.x;
    const int tree = blockIdx.x;
    const float* tb = times + (long)tree * NNODES;

    for (int idx = tid; idx < S; idx += 160) {
        Qw_s[idx] = Qw[idx];
        Qb_s[idx] = Qb[idx];
        Wb_s[idx] = Wb[idx];
    }
    for (int idx = tid; idx < S * S; idx += 160) {
        int o = idx / S, k = idx % S;
        Ww_s[k * 102 + o] = Ww[idx];
    }
    // level-5 h is already k-major: hA[k][r] = prev[k*32768 + tree*32 + r]
    for (int idx = tid; idx < 32 * S; idx += 160) {
        int k = idx / 32, r = idx % 32;
        hA[k * 34 + r] = prev[(long)k * (NTREES * 32) + tree * 32 + r];
    }
    __syncthreads();

    const int rg = tid / 10;
    const int cg = tid % 10;
    const int c0 = cg * 10;

    float* hin  = hA;
    float* hout = hB;

    for (int d = 4; d >= 0; d--) {
        int M = 1 << d;
        if (rg < M) {
            u64 acc[5] = {0, 0, 0, 0, 0};
#pragma unroll 2
            for (int k = 0; k < S; k++) {
                float2 hp = *(const float2*)&hin[k * 34 + 2 * rg];
                float a = hp.x + hp.y;
                u64 A = pack2(a, a);
                const u64* wrow = (const u64*)&Ww_s[k * 102 + c0];
#pragma unroll
                for (int c = 0; c < 5; c++)
                    acc[c] = fma2(A, wrow[c], acc[c]);
            }
            float t = tb[M - 1 + rg];
#pragma unroll
            for (int c = 0; c < 5; c++) {
                float v0, v1;
                unpack2(acc[c], v0, v1);
                int o = c0 + 2 * c;
                hout[o * 34 + rg]       = fmaxf(v0 + Wb_s[o]     + fmaf(t, Qw_s[o],     Qb_s[o]),     0.f);
                hout[(o + 1) * 34 + rg] = fmaxf(v1 + Wb_s[o + 1] + fmaf(t, Qw_s[o + 1], Qb_s[o + 1]), 0.f);
            }
        }
        __syncthreads();
        float* tmp = hin; hin = hout; hout = tmp;
    }

    int p    = tid >> 5;
    int lane = tid & 31;
    float s = 0.f;
    for (int o = lane; o < S; o += 32)
        s = fmaf(hin[o * 34], Pw[p * S + o], s);
#pragma unroll
    for (int off = 16; off; off >>= 1)
        s += __shfl_down_sync(0xffffffffu, s, off);
    if (lane == 0)
        out[tree * 5 + p] = s + Pb[p];
}

// ---------------------------------------------------------------------------
extern "C" void kernel_launch(void* const* d_in, const int* in_sizes, int n_in,
                              void* d_out, int out_size)
{
    const float* times = (const float*)d_in[0];
    const float* Qw    = (const float*)d_in[1];
    const float* Qb    = (const float*)d_in[2];
    const float* Ww    = (const float*)d_in[3];
    const float* Wb    = (const float*)d_in[4];
    const float* Pw    = (const float*)d_in[5];
    const float* Pb    = (const float*)d_in[6];
    float* out = (float*)d_out;

    float *pA = nullptr, *pB = nullptr;
    cudaGetSymbolAddress((void**)&pA, g_bufA);
    cudaGetSymbolAddress((void**)&pB, g_bufB);

    cudaFuncSetAttribute(level_kernel<true>,
                         cudaFuncAttributeMaxDynamicSharedMemorySize, MAIN_SMEM);
    cudaFuncSetAttribute(level_kernel<false>,
                         cudaFuncAttributeMaxDynamicSharedMemorySize, MAIN_SMEM);
    cudaFuncSetAttribute(tree_kernel,
                         cudaFuncAttributeMaxDynamicSharedMemorySize, TREE_SMEM);

    // Level 8 (leaves fused) -> A
    level_kernel<true><<<(NTREES * 256) / TM, NTH, MAIN_SMEM>>>(
        times, Qw, Qb, Ww, Wb, nullptr, pA, 8);
    // Level 7: A -> B
    level_kernel<false><<<(NTREES * 128) / TM, NTH, MAIN_SMEM>>>(
        times, Qw, Qb, Ww, Wb, pA, pB, 7);
    // Level 6: B -> A
    level_kernel<false><<<(NTREES * 64) / TM, NTH, MAIN_SMEM>>>(
        times, Qw, Qb, Ww, Wb, pB, pA, 6);
    // Level 5: A -> B
    level_kernel<false><<<(NTREES * 32) / TM, NTH, MAIN_SMEM>>>(
        times, Qw, Qb, Ww, Wb, pA, pB, 5);

    // Levels 4..0 + projection
    tree_kernel<<<NTREES, 160, TREE_SMEM>>>(
        times, Qw, Qb, Ww, Wb, Pw, Pb, pB, out);
}

// round 10
// speedup vs baseline: 1.6195x; 1.1328x over previous
#include <cuda_runtime.h>

// gRNN over 1024 complete binary trees, depth 10, hidden SIZE=100.
// h is K-MAJOR in gmem between levels: h[o][node], node fastest.
// L8 (leaf-fused), L7: TM=128 f32x2 GEMM, 3 CTAs/SM.
// L6: TM=64 variant, 4 CTAs/SM (fixes wave quantization).
// L5..L0 + projection: one fused per-tree subtree kernel.

#define S        100
#define OP       100     // Ww_s row stride, k-major [k][o]
#define KH       50      // k-half size (split-K staging)
#define NTH      320
#define NTREES   1024
#define NNODES   1023

typedef unsigned long long u64;

// Ping-pong level buffers, k-major: buf[o * M + node].
__device__ float g_bufA[NTREES * 256 * S];   // levels 8, 6
__device__ float g_bufB[NTREES * 128 * S];   // level 7

__device__ __forceinline__ u64 pack2(float x, float y) {
    u64 r; asm("mov.b64 %0, {%1,%2};" : "=l"(r) : "f"(x), "f"(y)); return r;
}
__device__ __forceinline__ void unpack2(u64 v, float& x, float& y) {
    asm("mov.b64 {%0,%1}, %2;" : "=f"(x), "=f"(y) : "l"(v));
}
__device__ __forceinline__ u64 fma2(u64 a, u64 b, u64 c) {
    u64 d; asm("fma.rn.f32x2 %0, %1, %2, %3;" : "=l"(d) : "l"(a), "l"(b), "l"(c));
    return d;
}

#define MAIN_SMEM(TMv) ((S*OP + KH*((TMv)+4) + 3*S) * (int)sizeof(float))
#define SUB_SMEM ((S*102 + S*66 + S*34 + 3*S) * (int)sizeof(float))

// ---------------------------------------------------------------------------
// Level kernel. prev/cur k-major. lane -> R rows, warp -> 10 cols.
// TMv=128: R=4, 3 CTAs/SM.  TMv=64: R=2, 4 CTAs/SM.
// ---------------------------------------------------------------------------
template<int TMv, bool LEAF>
__global__ __launch_bounds__(NTH, TMv == 128 ? 3 : 4)
void level_kernel(const float* __restrict__ times,
                  const float* __restrict__ Qw,
                  const float* __restrict__ Qb,
                  const float* __restrict__ Ww,
                  const float* __restrict__ Wb,
                  const float* __restrict__ prev,
                  float* __restrict__ cur,
                  int d)
{
    constexpr int R    = TMv / 32;
    constexpr int TMPv = TMv + 4;

    extern __shared__ float sm[];
    float* Ww_s   = sm;                 // [S][OP]  k-major
    float* comb_s = Ww_s + S * OP;      // [KH][TMPv]
    float* Qw_s   = comb_s + KH * TMPv;
    float* Qb_s   = Qw_s + S;
    float* Wb_s   = Qb_s + S;

    const int  tid     = threadIdx.x;
    const int  lvl     = 1 << d;
    const int  M       = NTREES << d;       // rows this level
    const long Mprev   = (long)M * 2;
    const int  baseRow = blockIdx.x * TMv;

    for (int idx = tid; idx < S; idx += NTH) {
        Qw_s[idx] = Qw[idx];
        Qb_s[idx] = Qb[idx];
        Wb_s[idx] = Wb[idx];
    }
    for (int idx = tid; idx < S * S; idx += NTH) {
        int o = idx / S, k = idx % S;
        Ww_s[k * OP + o] = Ww[idx];
    }

    const int lane = tid & 31;
    const int warp = tid >> 5;
    const int r0 = lane * R;
    const int c0 = warp * 10;

    u64 acc[R][5];
#pragma unroll
    for (int r = 0; r < R; r++)
#pragma unroll
        for (int c = 0; c < 5; c++) acc[r][c] = 0ull;

    __syncthreads();   // Ww_s / Qw_s ready

#pragma unroll 1
    for (int half = 0; half < 2; half++) {
        const int k0 = half * KH;

        // ---- build comb half: comb_s[kk][r] = h_left + h_right ----
        if (LEAF) {
            for (int idx = tid; idx < KH * TMv; idx += NTH) {
                int kk = idx / TMv, r = idx % TMv;
                int k = k0 + kk;
                int g = baseRow + r;
                int b = g >> d;
                int n = g & (lvl - 1);
                const float* tb = times + (long)b * NNODES;
                float tL = tb[2 * lvl - 1 + 2 * n];
                float tR = tb[2 * lvl + 2 * n];
                float qw = Qw_s[k], qb = Qb_s[k];
                comb_s[kk * TMPv + r] = fmaxf(fmaf(tL, qw, qb), 0.f)
                                      + fmaxf(fmaf(tR, qw, qb), 0.f);
            }
        } else {
            for (int idx = tid; idx < KH * (TMv / 8); idx += NTH) {
                int kk = idx / (TMv / 8), r8 = idx % (TMv / 8);
                const float* p = prev + (long)(k0 + kk) * Mprev
                                      + 2 * (long)(baseRow + 8 * r8);
                float4 v0 = *(const float4*)(p + 0);
                float4 v1 = *(const float4*)(p + 4);
                float4 v2 = *(const float4*)(p + 8);
                float4 v3 = *(const float4*)(p + 12);
                float* cs = &comb_s[kk * TMPv + 8 * r8];
                *(float4*)(cs + 0) = make_float4(v0.x + v0.y, v0.z + v0.w,
                                                 v1.x + v1.y, v1.z + v1.w);
                *(float4*)(cs + 4) = make_float4(v2.x + v2.y, v2.z + v2.w,
                                                 v3.x + v3.y, v3.z + v3.w);
            }
        }
        __syncthreads();

        // ---- packed-f32x2 GEMM over this k-half ----
#pragma unroll 2
        for (int kk = 0; kk < KH; kk++) {
            u64 A[R];
            if constexpr (R == 4) {
                const float4 a4 = *(const float4*)&comb_s[kk * TMPv + r0];
                A[0] = pack2(a4.x, a4.x);
                A[1] = pack2(a4.y, a4.y);
                A[2] = pack2(a4.z, a4.z);
                A[3] = pack2(a4.w, a4.w);
            } else {
                const float2 a2 = *(const float2*)&comb_s[kk * TMPv + r0];
                A[0] = pack2(a2.x, a2.x);
                A[1] = pack2(a2.y, a2.y);
            }
            const u64* wrow = (const u64*)&Ww_s[(k0 + kk) * OP + c0]; // warp-uniform
#pragma unroll
            for (int c = 0; c < 5; c++) {
                u64 B = wrow[c];
#pragma unroll
                for (int r = 0; r < R; r++)
                    acc[r][c] = fma2(A[r], B, acc[r][c]);
            }
        }
        __syncthreads();   // before rebuilding comb_s
    }

    // ---- epilogue: + Wb + t*Qw + Qb, relu; k-major coalesced stores ----
    float tv[R];
#pragma unroll
    for (int r = 0; r < R; r++) {
        int g = baseRow + r0 + r;
        int b = g >> d;
        int n = g & (lvl - 1);
        tv[r] = times[(long)b * NNODES + (lvl - 1) + n];
    }
    const long g0 = baseRow + r0;
#pragma unroll
    for (int c = 0; c < 5; c++) {
        int o0 = c0 + 2 * c;
        float x[R], y[R];
#pragma unroll
        for (int r = 0; r < R; r++) unpack2(acc[r][c], x[r], y[r]);
        float h0[R], h1[R];
#pragma unroll
        for (int r = 0; r < R; r++) {
            h0[r] = fmaxf(x[r] + Wb_s[o0]   + fmaf(tv[r], Qw_s[o0],   Qb_s[o0]),   0.f);
            h1[r] = fmaxf(y[r] + Wb_s[o0+1] + fmaf(tv[r], Qw_s[o0+1], Qb_s[o0+1]), 0.f);
        }
        if constexpr (R == 4) {
            *(float4*)&cur[(long)o0 * M + g0]       = make_float4(h0[0], h0[1], h0[2], h0[3]);
            *(float4*)&cur[(long)(o0 + 1) * M + g0] = make_float4(h1[0], h1[1], h1[2], h1[3]);
        } else {
            *(float2*)&cur[(long)o0 * M + g0]       = make_float2(h0[0], h0[1]);
            *(float2*)&cur[(long)(o0 + 1) * M + g0] = make_float2(h1[0], h1[1]);
        }
    }
}

// ---------------------------------------------------------------------------
// Subtree kernel: one CTA per tree, levels 5..0 + projection.
// prev = level-6 h, k-major [k][65536]. 320 threads: rg=tid/10 rows, 10 cols.
// h ping-pong: X stride 66 (<=64 nodes), Y stride 34 (<=32 nodes).
// ---------------------------------------------------------------------------
__global__ __launch_bounds__(NTH, 2)
void subtree_kernel(const float* __restrict__ times,
                    const float* __restrict__ Qw,
                    const float* __restrict__ Qb,
                    const float* __restrict__ Ww,
                    const float* __restrict__ Wb,
                    const float* __restrict__ Pw,
                    const float* __restrict__ Pb,
                    const float* __restrict__ prev,
                    float* __restrict__ out)
{
    extern __shared__ float sm[];
    float* Ww_s = sm;                  // [S][102]
    float* X    = Ww_s + S * 102;      // [S][66]
    float* Y    = X + S * 66;          // [S][34]
    float* Qw_s = Y + S * 34;
    float* Qb_s = Qw_s + S;
    float* Wb_s = Qb_s + S;

    const int tid  = threadIdx.x;
    const int tree = blockIdx.x;
    const float* tb = times + (long)tree * NNODES;
    const long M6 = (long)NTREES * 64;

    for (int idx = tid; idx < S; idx += NTH) {
        Qw_s[idx] = Qw[idx];
        Qb_s[idx] = Qb[idx];
        Wb_s[idx] = Wb[idx];
    }
    for (int idx = tid; idx < S * S; idx += NTH) {
        int o = idx / S, k = idx % S;
        Ww_s[k * 102 + o] = Ww[idx];
    }
    // stage level-6 h: X[k][r] = prev[k*M6 + tree*64 + r]  (coalesced in r)
    for (int idx = tid; idx < 64 * S; idx += NTH) {
        int k = idx / 64, r = idx % 64;
        X[k * 66 + r] = prev[(long)k * M6 + tree * 64 + r];
    }
    __syncthreads();

    const int rg = tid / 10;       // 0..31
    const int cg = tid % 10;
    const int c0 = cg * 10;

    float* hin  = X;  int is = 66;
    float* hout = Y;  int os = 34;

#pragma unroll 1
    for (int d = 5; d >= 0; d--) {
        const int Mout = 1 << d;
        if (rg < Mout) {
            u64 acc[5] = {0, 0, 0, 0, 0};
#pragma unroll 2
            for (int k = 0; k < S; k++) {
                float2 hp = *(const float2*)&hin[k * is + 2 * rg];
                float a = hp.x + hp.y;
                u64 A = pack2(a, a);
                const u64* wrow = (const u64*)&Ww_s[k * 102 + c0];
#pragma unroll
                for (int c = 0; c < 5; c++)
                    acc[c] = fma2(A, wrow[c], acc[c]);
            }
            float t = tb[Mout - 1 + rg];
#pragma unroll
            for (int c = 0; c < 5; c++) {
                float v0, v1;
                unpack2(acc[c], v0, v1);
                int o = c0 + 2 * c;
                hout[o * os + rg]       = fmaxf(v0 + Wb_s[o]     + fmaf(t, Qw_s[o],     Qb_s[o]),     0.f);
                hout[(o + 1) * os + rg] = fmaxf(v1 + Wb_s[o + 1] + fmaf(t, Qw_s[o + 1], Qb_s[o + 1]), 0.f);
            }
        }
        __syncthreads();
        float* tp = hin; hin = hout; hout = tp;
        int ts = is; is = os; os = ts;
    }

    // root h now in hin (stride is), node 0: hin[o * is]
    int p    = tid >> 5;       // warp id 0..9; only 0..4 project
    int lane = tid & 31;
    if (p < 5) {
        float s = 0.f;
        for (int o = lane; o < S; o += 32)
            s = fmaf(hin[o * is], Pw[p * S + o], s);
#pragma unroll
        for (int off = 16; off; off >>= 1)
            s += __shfl_down_sync(0xffffffffu, s, off);
        if (lane == 0)
            out[tree * 5 + p] = s + Pb[p];
    }
}

// ---------------------------------------------------------------------------
extern "C" void kernel_launch(void* const* d_in, const int* in_sizes, int n_in,
                              void* d_out, int out_size)
{
    const float* times = (const float*)d_in[0];
    const float* Qw    = (const float*)d_in[1];
    const float* Qb    = (const float*)d_in[2];
    const float* Ww    = (const float*)d_in[3];
    const float* Wb    = (const float*)d_in[4];
    const float* Pw    = (const float*)d_in[5];
    const float* Pb    = (const float*)d_in[6];
    float* out = (float*)d_out;

    float *pA = nullptr, *pB = nullptr;
    cudaGetSymbolAddress((void**)&pA, g_bufA);
    cudaGetSymbolAddress((void**)&pB, g_bufB);

    cudaFuncSetAttribute(level_kernel<128, true>,
                         cudaFuncAttributeMaxDynamicSharedMemorySize, MAIN_SMEM(128));
    cudaFuncSetAttribute(level_kernel<128, false>,
                         cudaFuncAttributeMaxDynamicSharedMemorySize, MAIN_SMEM(128));
    cudaFuncSetAttribute(level_kernel<64, false>,
                         cudaFuncAttributeMaxDynamicSharedMemorySize, MAIN_SMEM(64));
    cudaFuncSetAttribute(subtree_kernel,
                         cudaFuncAttributeMaxDynamicSharedMemorySize, SUB_SMEM);

    // Level 8 (leaves fused) -> A   (M = 262144)
    level_kernel<128, true><<<(NTREES * 256) / 128, NTH, MAIN_SMEM(128)>>>(
        times, Qw, Qb, Ww, Wb, nullptr, pA, 8);
    // Level 7: A -> B               (M = 131072)
    level_kernel<128, false><<<(NTREES * 128) / 128, NTH, MAIN_SMEM(128)>>>(
        times, Qw, Qb, Ww, Wb, pA, pB, 7);
    // Level 6: B -> A, TM=64        (M = 65536, grid 1024, 4 CTAs/SM)
    level_kernel<64, false><<<(NTREES * 64) / 64, NTH, MAIN_SMEM(64)>>>(
        times, Qw, Qb, Ww, Wb, pB, pA, 6);

    // Levels 5..0 + projection: one CTA per tree
    subtree_kernel<<<NTREES, NTH, SUB_SMEM>>>(
        times, Qw, Qb, Ww, Wb, Pw, Pb, pA, out);
}

// round 11
// speedup vs baseline: 1.8536x; 1.1445x over previous
#include <cuda_runtime.h>

// gRNN over 1024 complete binary trees, depth 10, hidden SIZE=100.
// h is K-MAJOR in gmem between levels: h[o][node], node fastest.
// L8 (leaf-fused), L7: TM=128 f32x2 GEMM, 3 CTAs/SM.
// L6, L5: TM=64 variant, 4 CTAs/SM.
// L4..L0 + projection: tail kernel, 4 trees/CTA, grid 256 (single wave).

#define S        100
#define OP       100     // Ww_s row stride, k-major [k][o]
#define KH       50      // k-half size (split-K staging)
#define NTH      320
#define NTREES   1024
#define NNODES   1023
#define TPC      4       // trees per CTA in tail
#define HS       68      // tail h buffer stride (mult of 4)

typedef unsigned long long u64;

// Ping-pong level buffers, k-major: buf[o * M + node].
__device__ float g_bufA[NTREES * 256 * S];   // levels 8, 6
__device__ float g_bufB[NTREES * 128 * S];   // levels 7, 5

__device__ __forceinline__ u64 pack2(float x, float y) {
    u64 r; asm("mov.b64 %0, {%1,%2};" : "=l"(r) : "f"(x), "f"(y)); return r;
}
__device__ __forceinline__ void unpack2(u64 v, float& x, float& y) {
    asm("mov.b64 {%0,%1}, %2;" : "=f"(x), "=f"(y) : "l"(v));
}
__device__ __forceinline__ u64 fma2(u64 a, u64 b, u64 c) {
    u64 d; asm("fma.rn.f32x2 %0, %1, %2, %3;" : "=l"(d) : "l"(a), "l"(b), "l"(c));
    return d;
}

#define MAIN_SMEM(TMv) ((S*OP + KH*((TMv)+4) + 3*S) * (int)sizeof(float))
#define TAIL_SMEM ((S*102 + 2*S*HS + 3*S) * (int)sizeof(float))

// ---------------------------------------------------------------------------
// Level kernel. prev/cur k-major. lane -> R rows, warp -> 10 cols.
// TMv=128: R=4, 3 CTAs/SM.  TMv=64: R=2, 4 CTAs/SM.
// ---------------------------------------------------------------------------
template<int TMv, bool LEAF>
__global__ __launch_bounds__(NTH, TMv == 128 ? 3 : 4)
void level_kernel(const float* __restrict__ times,
                  const float* __restrict__ Qw,
                  const float* __restrict__ Qb,
                  const float* __restrict__ Ww,
                  const float* __restrict__ Wb,
                  const float* __restrict__ prev,
                  float* __restrict__ cur,
                  int d)
{
    constexpr int R    = TMv / 32;
    constexpr int TMPv = TMv + 4;

    extern __shared__ float sm[];
    float* Ww_s   = sm;                 // [S][OP]  k-major
    float* comb_s = Ww_s + S * OP;      // [KH][TMPv]
    float* Qw_s   = comb_s + KH * TMPv;
    float* Qb_s   = Qw_s + S;
    float* Wb_s   = Qb_s + S;

    const int  tid     = threadIdx.x;
    const int  lvl     = 1 << d;
    const int  M       = NTREES << d;       // rows this level
    const long Mprev   = (long)M * 2;
    const int  baseRow = blockIdx.x * TMv;

    for (int idx = tid; idx < S; idx += NTH) {
        Qw_s[idx] = Qw[idx];
        Qb_s[idx] = Qb[idx];
        Wb_s[idx] = Wb[idx];
    }
    for (int idx = tid; idx < S * S; idx += NTH) {
        int o = idx / S, k = idx % S;
        Ww_s[k * OP + o] = Ww[idx];
    }

    const int lane = tid & 31;
    const int warp = tid >> 5;
    const int r0 = lane * R;
    const int c0 = warp * 10;

    u64 acc[R][5];
#pragma unroll
    for (int r = 0; r < R; r++)
#pragma unroll
        for (int c = 0; c < 5; c++) acc[r][c] = 0ull;

    __syncthreads();   // Ww_s / Qw_s ready

#pragma unroll 1
    for (int half = 0; half < 2; half++) {
        const int k0 = half * KH;

        // ---- build comb half: comb_s[kk][r] = h_left + h_right ----
        if (LEAF) {
            for (int idx = tid; idx < KH * TMv; idx += NTH) {
                int kk = idx / TMv, r = idx % TMv;
                int k = k0 + kk;
                int g = baseRow + r;
                int b = g >> d;
                int n = g & (lvl - 1);
                const float* tb = times + (long)b * NNODES;
                float tL = tb[2 * lvl - 1 + 2 * n];
                float tR = tb[2 * lvl + 2 * n];
                float qw = Qw_s[k], qb = Qb_s[k];
                comb_s[kk * TMPv + r] = fmaxf(fmaf(tL, qw, qb), 0.f)
                                      + fmaxf(fmaf(tR, qw, qb), 0.f);
            }
        } else {
            for (int idx = tid; idx < KH * (TMv / 8); idx += NTH) {
                int kk = idx / (TMv / 8), r8 = idx % (TMv / 8);
                const float* p = prev + (long)(k0 + kk) * Mprev
                                      + 2 * (long)(baseRow + 8 * r8);
                float4 v0 = *(const float4*)(p + 0);
                float4 v1 = *(const float4*)(p + 4);
                float4 v2 = *(const float4*)(p + 8);
                float4 v3 = *(const float4*)(p + 12);
                float* cs = &comb_s[kk * TMPv + 8 * r8];
                *(float4*)(cs + 0) = make_float4(v0.x + v0.y, v0.z + v0.w,
                                                 v1.x + v1.y, v1.z + v1.w);
                *(float4*)(cs + 4) = make_float4(v2.x + v2.y, v2.z + v2.w,
                                                 v3.x + v3.y, v3.z + v3.w);
            }
        }
        __syncthreads();

        // ---- packed-f32x2 GEMM over this k-half ----
#pragma unroll 2
        for (int kk = 0; kk < KH; kk++) {
            u64 A[R];
            if constexpr (R == 4) {
                const float4 a4 = *(const float4*)&comb_s[kk * TMPv + r0];
                A[0] = pack2(a4.x, a4.x);
                A[1] = pack2(a4.y, a4.y);
                A[2] = pack2(a4.z, a4.z);
                A[3] = pack2(a4.w, a4.w);
            } else {
                const float2 a2 = *(const float2*)&comb_s[kk * TMPv + r0];
                A[0] = pack2(a2.x, a2.x);
                A[1] = pack2(a2.y, a2.y);
            }
            const u64* wrow = (const u64*)&Ww_s[(k0 + kk) * OP + c0]; // warp-uniform
#pragma unroll
            for (int c = 0; c < 5; c++) {
                u64 B = wrow[c];
#pragma unroll
                for (int r = 0; r < R; r++)
                    acc[r][c] = fma2(A[r], B, acc[r][c]);
            }
        }
        __syncthreads();   // before rebuilding comb_s
    }

    // ---- epilogue: + Wb + t*Qw + Qb, relu; k-major coalesced stores ----
    float tv[R];
#pragma unroll
    for (int r = 0; r < R; r++) {
        int g = baseRow + r0 + r;
        int b = g >> d;
        int n = g & (lvl - 1);
        tv[r] = times[(long)b * NNODES + (lvl - 1) + n];
    }
    const long g0 = baseRow + r0;
#pragma unroll
    for (int c = 0; c < 5; c++) {
        int o0 = c0 + 2 * c;
        float x[R], y[R];
#pragma unroll
        for (int r = 0; r < R; r++) unpack2(acc[r][c], x[r], y[r]);
        float h0[R], h1[R];
#pragma unroll
        for (int r = 0; r < R; r++) {
            h0[r] = fmaxf(x[r] + Wb_s[o0]   + fmaf(tv[r], Qw_s[o0],   Qb_s[o0]),   0.f);
            h1[r] = fmaxf(y[r] + Wb_s[o0+1] + fmaf(tv[r], Qw_s[o0+1], Qb_s[o0+1]), 0.f);
        }
        if constexpr (R == 4) {
            *(float4*)&cur[(long)o0 * M + g0]       = make_float4(h0[0], h0[1], h0[2], h0[3]);
            *(float4*)&cur[(long)(o0 + 1) * M + g0] = make_float4(h1[0], h1[1], h1[2], h1[3]);
        } else {
            *(float2*)&cur[(long)o0 * M + g0]       = make_float2(h0[0], h0[1]);
            *(float2*)&cur[(long)(o0 + 1) * M + g0] = make_float2(h1[0], h1[1]);
        }
    }
}

// ---------------------------------------------------------------------------
// Tail kernel: TPC=4 trees per CTA, levels 4..0 + projection. grid = 256.
// prev = level-5 h, k-major [k][32768].
// Row layout at level d: row r = t*(1<<d) + n, t in 0..3.  Children of row r
// at level d+1 are rows 2r, 2r+1 (contiguous) -> one aligned LDS pair.
// lane -> 2 rows (2*lane, 2*lane+1), warp -> 10 cols (warp-uniform B).
// ---------------------------------------------------------------------------
__global__ __launch_bounds__(NTH, 2)
void tail_kernel(const float* __restrict__ times,
                 const float* __restrict__ Qw,
                 const float* __restrict__ Qb,
                 const float* __restrict__ Ww,
                 const float* __restrict__ Wb,
                 const float* __restrict__ Pw,
                 const float* __restrict__ Pb,
                 const float* __restrict__ prev,
                 float* __restrict__ out)
{
    extern __shared__ float sm[];
    float* Ww_s = sm;                  // [S][102]
    float* bufA = Ww_s + S * 102;      // [S][HS]
    float* bufB = bufA + S * HS;       // [S][HS]
    float* Qw_s = bufB + S * HS;
    float* Qb_s = Qw_s + S;
    float* Wb_s = Qb_s + S;

    const int tid   = threadIdx.x;
    const int tree0 = blockIdx.x * TPC;
    const long M5   = (long)NTREES * 32;

    for (int idx = tid; idx < S; idx += NTH) {
        Qw_s[idx] = Qw[idx];
        Qb_s[idx] = Qb[idx];
        Wb_s[idx] = Wb[idx];
    }
    for (int idx = tid; idx < S * S; idx += NTH) {
        int o = idx / S, k = idx % S;
        Ww_s[k * 102 + o] = Ww[idx];
    }
    // Stage L4 comb directly: bufA[k][r] = h5[2n] + h5[2n+1], r = t*16 + n.
    for (int idx = tid; idx < 64 * S; idx += NTH) {
        int k = idx / 64, r = idx % 64;
        int t = r >> 4, n = r & 15;
        const float2 hp = *(const float2*)&prev[(long)k * M5 + (tree0 + t) * 32 + 2 * n];
        bufA[k * HS + r] = hp.x + hp.y;
    }
    __syncthreads();

    const int lane = tid & 31;
    const int warp = tid >> 5;
    const int c0   = warp * 10;
    const int r0   = 2 * lane;

    float* hin  = bufA;
    float* hout = bufB;

#pragma unroll 1
    for (int d = 4; d >= 0; d--) {
        const int Mout = TPC << d;     // 64, 32, 16, 8, 4
        if (r0 < Mout) {
            u64 acc[2][5];
#pragma unroll
            for (int r = 0; r < 2; r++)
#pragma unroll
                for (int c = 0; c < 5; c++) acc[r][c] = 0ull;

            if (d == 4) {
                // comb pre-folded: one float per row
#pragma unroll 2
                for (int k = 0; k < S; k++) {
                    const float2 a2 = *(const float2*)&hin[k * HS + r0];
                    u64 A0 = pack2(a2.x, a2.x);
                    u64 A1 = pack2(a2.y, a2.y);
                    const u64* wrow = (const u64*)&Ww_s[k * 102 + c0];
#pragma unroll
                    for (int c = 0; c < 5; c++) {
                        u64 B = wrow[c];
                        acc[0][c] = fma2(A0, B, acc[0][c]);
                        acc[1][c] = fma2(A1, B, acc[1][c]);
                    }
                }
            } else {
                // read child pairs: rows 2*r0 .. 2*r0+3 = one float4
#pragma unroll 2
                for (int k = 0; k < S; k++) {
                    const float4 h4 = *(const float4*)&hin[k * HS + 2 * r0];
                    float a0 = h4.x + h4.y;
                    float a1 = h4.z + h4.w;
                    u64 A0 = pack2(a0, a0);
                    u64 A1 = pack2(a1, a1);
                    const u64* wrow = (const u64*)&Ww_s[k * 102 + c0];
#pragma unroll
                    for (int c = 0; c < 5; c++) {
                        u64 B = wrow[c];
                        acc[0][c] = fma2(A0, B, acc[0][c]);
                        acc[1][c] = fma2(A1, B, acc[1][c]);
                    }
                }
            }

            // epilogue for rows r0, r0+1
            float tv[2];
#pragma unroll
            for (int r = 0; r < 2; r++) {
                int rr = r0 + r;
                int t = rr >> d, n = rr & ((1 << d) - 1);
                tv[r] = times[(long)(tree0 + t) * NNODES + (1 << d) - 1 + n];
            }
#pragma unroll
            for (int c = 0; c < 5; c++) {
                int o0 = c0 + 2 * c;
                float x0, y0, x1, y1;
                unpack2(acc[0][c], x0, y0);
                unpack2(acc[1][c], x1, y1);
                float h00 = fmaxf(x0 + Wb_s[o0]   + fmaf(tv[0], Qw_s[o0],   Qb_s[o0]),   0.f);
                float h01 = fmaxf(x1 + Wb_s[o0]   + fmaf(tv[1], Qw_s[o0],   Qb_s[o0]),   0.f);
                float h10 = fmaxf(y0 + Wb_s[o0+1] + fmaf(tv[0], Qw_s[o0+1], Qb_s[o0+1]), 0.f);
                float h11 = fmaxf(y1 + Wb_s[o0+1] + fmaf(tv[1], Qw_s[o0+1], Qb_s[o0+1]), 0.f);
                *(float2*)&hout[o0 * HS + r0]       = make_float2(h00, h01);
                *(float2*)&hout[(o0 + 1) * HS + r0] = make_float2(h10, h11);
            }
        }
        __syncthreads();
        float* tp = hin; hin = hout; hout = tp;
    }

    // Roots: hin[o*HS + t], t = 0..3. 20 outputs (4 trees x 5 params),
    // 2 per warp, lane-strided dot + shfl reduce.
#pragma unroll
    for (int j = 0; j < 2; j++) {
        int oidx = 2 * warp + j;       // 0..19
        int t = oidx / 5, p = oidx % 5;
        float s = 0.f;
        for (int o = lane; o < S; o += 32)
            s = fmaf(hin[o * HS + t], Pw[p * S + o], s);
#pragma unroll
        for (int off = 16; off; off >>= 1)
            s += __shfl_down_sync(0xffffffffu, s, off);
        if (lane == 0)
            out[(long)(tree0 + t) * 5 + p] = s + Pb[p];
    }
}

// ---------------------------------------------------------------------------
extern "C" void kernel_launch(void* const* d_in, const int* in_sizes, int n_in,
                              void* d_out, int out_size)
{
    const float* times = (const float*)d_in[0];
    const float* Qw    = (const float*)d_in[1];
    const float* Qb    = (const float*)d_in[2];
    const float* Ww    = (const float*)d_in[3];
    const float* Wb    = (const float*)d_in[4];
    const float* Pw    = (const float*)d_in[5];
    const float* Pb    = (const float*)d_in[6];
    float* out = (float*)d_out;

    float *pA = nullptr, *pB = nullptr;
    cudaGetSymbolAddress((void**)&pA, g_bufA);
    cudaGetSymbolAddress((void**)&pB, g_bufB);

    cudaFuncSetAttribute(level_kernel<128, true>,
                         cudaFuncAttributeMaxDynamicSharedMemorySize, MAIN_SMEM(128));
    cudaFuncSetAttribute(level_kernel<128, false>,
                         cudaFuncAttributeMaxDynamicSharedMemorySize, MAIN_SMEM(128));
    cudaFuncSetAttribute(level_kernel<64, false>,
                         cudaFuncAttributeMaxDynamicSharedMemorySize, MAIN_SMEM(64));
    cudaFuncSetAttribute(tail_kernel,
                         cudaFuncAttributeMaxDynamicSharedMemorySize, TAIL_SMEM);

    // Level 8 (leaves fused) -> A   (M = 262144, grid 2048)
    level_kernel<128, true><<<(NTREES * 256) / 128, NTH, MAIN_SMEM(128)>>>(
        times, Qw, Qb, Ww, Wb, nullptr, pA, 8);
    // Level 7: A -> B               (M = 131072, grid 1024)
    level_kernel<128, false><<<(NTREES * 128) / 128, NTH, MAIN_SMEM(128)>>>(
        times, Qw, Qb, Ww, Wb, pA, pB, 7);
    // Level 6: B -> A, TM=64        (M = 65536, grid 1024)
    level_kernel<64, false><<<(NTREES * 64) / 64, NTH, MAIN_SMEM(64)>>>(
        times, Qw, Qb, Ww, Wb, pB, pA, 6);
    // Level 5: A -> B, TM=64        (M = 32768, grid 512)
    level_kernel<64, false><<<(NTREES * 32) / 64, NTH, MAIN_SMEM(64)>>>(
        times, Qw, Qb, Ww, Wb, pA, pB, 5);

    // Levels 4..0 + projection: 4 trees/CTA, grid 256 (single wave)
    tail_kernel<<<NTREES / TPC, NTH, TAIL_SMEM>>>(
        times, Qw, Qb, Ww, Wb, Pw, Pb, pB, out);
}

// round 12
// speedup vs baseline: 1.9023x; 1.0263x over previous
#include <cuda_runtime.h>
#include <cstdint>

// gRNN over 1024 complete binary trees, depth 10, hidden SIZE=100.
// Between levels we store COMB (pair-sums), k-major: comb[o][m], m fastest.
// All GEMM levels: TM=64, R=2, 320 thr, 3 CTAs/SM, cp.async A-tile staging,
// no mid-kernel barriers. L4..L0 + projection: tail kernel, 4 trees/CTA.

#define S      100
#define OP     100     // Ww_s row stride, k-major [k][o]
#define TM     64      // node rows per CTA
#define NTH    320
#define NTREES 1024
#define NNODES 1023
#define TPC    4       // trees per CTA in tail
#define HS     68      // tail h buffer stride

typedef unsigned long long u64;

// comb buffers (k-major, comb_L has NTREES<<L entries per o):
// bufB: comb7 (13.1M), later comb5 (3.28M). bufA: comb6 (6.55M), later comb4 (1.64M).
__device__ float g_bufA[NTREES * 64 * S];    // 6.55M floats
__device__ float g_bufB[NTREES * 128 * S];   // 13.1M floats

__device__ __forceinline__ u64 pack2(float x, float y) {
    u64 r; asm("mov.b64 %0, {%1,%2};" : "=l"(r) : "f"(x), "f"(y)); return r;
}
__device__ __forceinline__ void unpack2(u64 v, float& x, float& y) {
    asm("mov.b64 {%0,%1}, %2;" : "=f"(x), "=f"(y) : "l"(v));
}
__device__ __forceinline__ u64 fma2(u64 a, u64 b, u64 c) {
    u64 d; asm("fma.rn.f32x2 %0, %1, %2, %3;" : "=l"(d) : "l"(a), "l"(b), "l"(c));
    return d;
}
__device__ __forceinline__ void cpa16(uint32_t dst, const float* src) {
    asm volatile("cp.async.cg.shared.global [%0], [%1], 16;" :: "r"(dst), "l"(src));
}
__device__ __forceinline__ void cpa_commit() { asm volatile("cp.async.commit_group;" ::: "memory"); }
__device__ __forceinline__ void cpa_wait0()  { asm volatile("cp.async.wait_group 0;" ::: "memory"); }

#define LEVEL_SMEM ((S*OP + S*TM + 3*S + 128) * (int)sizeof(float))
#define TAIL_SMEM  ((S*102 + 2*S*HS + 3*S) * (int)sizeof(float))

// ---------------------------------------------------------------------------
// Level kernel (TM=64). combprev: prebuilt A-tile source [k][M] (non-leaf).
// Writes combnext[o][m] = h[o][2m] + h[o][2m+1]  (pair-sum for next level).
// lane -> 2 rows, warp -> 10 cols (warp-uniform B loads).
// ---------------------------------------------------------------------------
template<bool LEAF>
__global__ __launch_bounds__(NTH, 3)
void level64(const float* __restrict__ times,
             const float* __restrict__ Qw,
             const float* __restrict__ Qb,
             const float* __restrict__ Ww,
             const float* __restrict__ Wb,
             const float* __restrict__ combprev,
             float* __restrict__ combnext,
             int d)
{
    extern __shared__ float sm[];
    float* Ww_s   = sm;                 // [S][OP] k-major
    float* comb_s = Ww_s + S * OP;      // [S][TM]
    float* Qw_s   = comb_s + S * TM;
    float* Qb_s   = Qw_s + S;
    float* Wb_s   = Qb_s + S;
    float* t_s    = Wb_s + S;           // [128] leaf only

    const int tid     = threadIdx.x;
    const int lvl     = 1 << d;
    const int M       = NTREES << d;
    const int baseRow = blockIdx.x * TM;

    if (!LEAF) {
        // A-tile: 100x64 floats = 1600 16B-chunks, 5 per thread, async.
        uint32_t cbase = (uint32_t)__cvta_generic_to_shared(comb_s);
#pragma unroll
        for (int i = 0; i < 5; i++) {
            int idx = tid + i * NTH;            // 0..1599
            int k = idx >> 4, j = (idx & 15) << 2;
            cpa16(cbase + (uint32_t)(k * TM + j) * 4u,
                  combprev + (long)k * M + baseRow + j);
        }
        cpa_commit();
    }

    // stage weights (overlaps cp.async latency)
    for (int idx = tid; idx < S; idx += NTH) {
        Qw_s[idx] = Qw[idx];
        Qb_s[idx] = Qb[idx];
        Wb_s[idx] = Wb[idx];
    }
    for (int idx = tid; idx < S * S; idx += NTH) {
        int o = idx / S, k = idx % S;
        Ww_s[k * OP + o] = Ww[idx];
    }

    if (LEAF) {
        // children times of rows baseRow..baseRow+63: 128 contiguous floats
        int b  = baseRow >> 8;              // d=8: 256 nodes/tree, TM=64 divides
        int n0 = baseRow & 255;
        const float* tc = times + (long)b * NNODES + (2 * lvl - 1) + 2 * n0;
        if (tid < 128) t_s[tid] = tc[tid];
        __syncthreads();
        for (int idx = tid; idx < S * TM; idx += NTH) {
            int k = idx >> 6, r = idx & 63;
            float qw = Qw_s[k], qb = Qb_s[k];
            comb_s[idx] = fmaxf(fmaf(t_s[2 * r],     qw, qb), 0.f)
                        + fmaxf(fmaf(t_s[2 * r + 1], qw, qb), 0.f);
        }
        __syncthreads();
    } else {
        cpa_wait0();
        __syncthreads();
    }

    // ---- packed-f32x2 GEMM, straight through k=0..99, no barriers ----
    const int lane = tid & 31;
    const int warp = tid >> 5;
    const int r0 = 2 * lane;
    const int c0 = warp * 10;

    u64 acc[2][5];
#pragma unroll
    for (int r = 0; r < 2; r++)
#pragma unroll
        for (int c = 0; c < 5; c++) acc[r][c] = 0ull;

#pragma unroll 4
    for (int k = 0; k < S; k++) {
        const float2 a2 = *(const float2*)&comb_s[k * TM + r0];
        u64 A0 = pack2(a2.x, a2.x);
        u64 A1 = pack2(a2.y, a2.y);
        const u64* wrow = (const u64*)&Ww_s[k * OP + c0];   // warp-uniform
#pragma unroll
        for (int c = 0; c < 5; c++) {
            u64 B = wrow[c];
            acc[0][c] = fma2(A0, B, acc[0][c]);
            acc[1][c] = fma2(A1, B, acc[1][c]);
        }
    }

    // ---- epilogue: h = relu(acc + Wb + t*Qw + Qb); store pair-sum ----
    float tv[2];
#pragma unroll
    for (int r = 0; r < 2; r++) {
        int g = baseRow + r0 + r;
        int b = g >> d;
        int n = g & (lvl - 1);
        tv[r] = times[(long)b * NNODES + (lvl - 1) + n];
    }
    const int Mn = M >> 1;
    const int m  = (baseRow >> 1) + lane;
#pragma unroll
    for (int c = 0; c < 5; c++) {
        int o0 = c0 + 2 * c;
        float x0, y0, x1, y1;
        unpack2(acc[0][c], x0, y0);
        unpack2(acc[1][c], x1, y1);
        float h00 = fmaxf(x0 + Wb_s[o0]     + fmaf(tv[0], Qw_s[o0],     Qb_s[o0]),     0.f);
        float h01 = fmaxf(x1 + Wb_s[o0]     + fmaf(tv[1], Qw_s[o0],     Qb_s[o0]),     0.f);
        float h10 = fmaxf(y0 + Wb_s[o0 + 1] + fmaf(tv[0], Qw_s[o0 + 1], Qb_s[o0 + 1]), 0.f);
        float h11 = fmaxf(y1 + Wb_s[o0 + 1] + fmaf(tv[1], Qw_s[o0 + 1], Qb_s[o0 + 1]), 0.f);
        combnext[(long)o0 * Mn + m]       = h00 + h01;   // coalesced STG.32
        combnext[(long)(o0 + 1) * Mn + m] = h10 + h11;
    }
}

// ---------------------------------------------------------------------------
// Tail kernel: TPC=4 trees per CTA, levels 4..0 + projection. grid = 256.
// prev = comb4, k-major [k][16384] (prebuilt pair-sums). cp.async staged.
// ---------------------------------------------------------------------------
__global__ __launch_bounds__(NTH, 2)
void tail_kernel(const float* __restrict__ times,
                 const float* __restrict__ Qw,
                 const float* __restrict__ Qb,
                 const float* __restrict__ Ww,
                 const float* __restrict__ Wb,
                 const float* __restrict__ Pw,
                 const float* __restrict__ Pb,
                 const float* __restrict__ prev,
                 float* __restrict__ out)
{
    extern __shared__ float sm[];
    float* Ww_s = sm;                  // [S][102]
    float* bufA = Ww_s + S * 102;      // [S][HS]
    float* bufB = bufA + S * HS;       // [S][HS]
    float* Qw_s = bufB + S * HS;
    float* Qb_s = Qw_s + S;
    float* Wb_s = Qb_s + S;

    const int tid   = threadIdx.x;
    const int tree0 = blockIdx.x * TPC;
    const int M4    = NTREES * 16;

    // stage comb4 rows (64 per CTA) via cp.async
    {
        uint32_t abase = (uint32_t)__cvta_generic_to_shared(bufA);
#pragma unroll
        for (int i = 0; i < 5; i++) {
            int idx = tid + i * NTH;            // 0..1599
            int k = idx >> 4, j = (idx & 15) << 2;
            cpa16(abase + (uint32_t)(k * HS + j) * 4u,
                  prev + (long)k * M4 + tree0 * 16 + j);
        }
        cpa_commit();
    }

    for (int idx = tid; idx < S; idx += NTH) {
        Qw_s[idx] = Qw[idx];
        Qb_s[idx] = Qb[idx];
        Wb_s[idx] = Wb[idx];
    }
    for (int idx = tid; idx < S * S; idx += NTH) {
        int o = idx / S, k = idx % S;
        Ww_s[k * 102 + o] = Ww[idx];
    }
    cpa_wait0();
    __syncthreads();

    const int lane = tid & 31;
    const int warp = tid >> 5;
    const int c0   = warp * 10;
    const int r0   = 2 * lane;

    float* hin  = bufA;
    float* hout = bufB;

#pragma unroll 1
    for (int d = 4; d >= 0; d--) {
        const int Mout = TPC << d;     // 64, 32, 16, 8, 4
        if (r0 < Mout) {
            u64 acc[2][5];
#pragma unroll
            for (int r = 0; r < 2; r++)
#pragma unroll
                for (int c = 0; c < 5; c++) acc[r][c] = 0ull;

            if (d == 4) {
                // comb prebuilt: one float per row
#pragma unroll 2
                for (int k = 0; k < S; k++) {
                    const float2 a2 = *(const float2*)&hin[k * HS + r0];
                    u64 A0 = pack2(a2.x, a2.x);
                    u64 A1 = pack2(a2.y, a2.y);
                    const u64* wrow = (const u64*)&Ww_s[k * 102 + c0];
#pragma unroll
                    for (int c = 0; c < 5; c++) {
                        u64 B = wrow[c];
                        acc[0][c] = fma2(A0, B, acc[0][c]);
                        acc[1][c] = fma2(A1, B, acc[1][c]);
                    }
                }
            } else {
                // read child h pairs: rows 2*r0 .. 2*r0+3 = one float4
#pragma unroll 2
                for (int k = 0; k < S; k++) {
                    const float4 h4 = *(const float4*)&hin[k * HS + 2 * r0];
                    float a0 = h4.x + h4.y;
                    float a1 = h4.z + h4.w;
                    u64 A0 = pack2(a0, a0);
                    u64 A1 = pack2(a1, a1);
                    const u64* wrow = (const u64*)&Ww_s[k * 102 + c0];
#pragma unroll
                    for (int c = 0; c < 5; c++) {
                        u64 B = wrow[c];
                        acc[0][c] = fma2(A0, B, acc[0][c]);
                        acc[1][c] = fma2(A1, B, acc[1][c]);
                    }
                }
            }

            float tv[2];
#pragma unroll
            for (int r = 0; r < 2; r++) {
                int rr = r0 + r;
                int t = rr >> d, n = rr & ((1 << d) - 1);
                tv[r] = times[(long)(tree0 + t) * NNODES + (1 << d) - 1 + n];
            }
#pragma unroll
            for (int c = 0; c < 5; c++) {
                int o0 = c0 + 2 * c;
                float x0, y0, x1, y1;
                unpack2(acc[0][c], x0, y0);
                unpack2(acc[1][c], x1, y1);
                float h00 = fmaxf(x0 + Wb_s[o0]   + fmaf(tv[0], Qw_s[o0],   Qb_s[o0]),   0.f);
                float h01 = fmaxf(x1 + Wb_s[o0]   + fmaf(tv[1], Qw_s[o0],   Qb_s[o0]),   0.f);
                float h10 = fmaxf(y0 + Wb_s[o0+1] + fmaf(tv[0], Qw_s[o0+1], Qb_s[o0+1]), 0.f);
                float h11 = fmaxf(y1 + Wb_s[o0+1] + fmaf(tv[1], Qw_s[o0+1], Qb_s[o0+1]), 0.f);
                *(float2*)&hout[o0 * HS + r0]       = make_float2(h00, h01);
                *(float2*)&hout[(o0 + 1) * HS + r0] = make_float2(h10, h11);
            }
        }
        __syncthreads();
        float* tp = hin; hin = hout; hout = tp;
    }

    // Roots: hin[o*HS + t], t = 0..3. 20 outputs, 2 per warp.
#pragma unroll
    for (int j = 0; j < 2; j++) {
        int oidx = 2 * warp + j;       // 0..19
        int t = oidx / 5, p = oidx % 5;
        float s = 0.f;
        for (int o = lane; o < S; o += 32)
            s = fmaf(hin[o * HS + t], Pw[p * S + o], s);
#pragma unroll
        for (int off = 16; off; off >>= 1)
            s += __shfl_down_sync(0xffffffffu, s, off);
        if (lane == 0)
            out[(long)(tree0 + t) * 5 + p] = s + Pb[p];
    }
}

// ---------------------------------------------------------------------------
extern "C" void kernel_launch(void* const* d_in, const int* in_sizes, int n_in,
                              void* d_out, int out_size)
{
    const float* times = (const float*)d_in[0];
    const float* Qw    = (const float*)d_in[1];
    const float* Qb    = (const float*)d_in[2];
    const float* Ww    = (const float*)d_in[3];
    const float* Wb    = (const float*)d_in[4];
    const float* Pw    = (const float*)d_in[5];
    const float* Pb    = (const float*)d_in[6];
    float* out = (float*)d_out;

    float *pA = nullptr, *pB = nullptr;
    cudaGetSymbolAddress((void**)&pA, g_bufA);
    cudaGetSymbolAddress((void**)&pB, g_bufB);

    cudaFuncSetAttribute(level64<true>,
                         cudaFuncAttributeMaxDynamicSharedMemorySize, LEVEL_SMEM);
    cudaFuncSetAttribute(level64<false>,
                         cudaFuncAttributeMaxDynamicSharedMemorySize, LEVEL_SMEM);
    cudaFuncSetAttribute(tail_kernel,
                         cudaFuncAttributeMaxDynamicSharedMemorySize, TAIL_SMEM);

    // L8 (leaf comb from times) -> comb7 in bufB   (M=262144, grid 4096)
    level64<true><<<(NTREES * 256) / TM, NTH, LEVEL_SMEM>>>(
        times, Qw, Qb, Ww, Wb, nullptr, pB, 8);
    // L7: comb7 -> comb6 in bufA                   (M=131072, grid 2048)
    level64<false><<<(NTREES * 128) / TM, NTH, LEVEL_SMEM>>>(
        times, Qw, Qb, Ww, Wb, pB, pA, 7);
    // L6: comb6 -> comb5 in bufB                   (M=65536, grid 1024)
    level64<false><<<(NTREES * 64) / TM, NTH, LEVEL_SMEM>>>(
        times, Qw, Qb, Ww, Wb, pA, pB, 6);
    // L5: comb5 -> comb4 in bufA                   (M=32768, grid 512)
    level64<false><<<(NTREES * 32) / TM, NTH, LEVEL_SMEM>>>(
        times, Qw, Qb, Ww, Wb, pB, pA, 5);

    // L4..L0 + projection: 4 trees/CTA, grid 256
    tail_kernel<<<NTREES / TPC, NTH, TAIL_SMEM>>>(
        times, Qw, Qb, Ww, Wb, Pw, Pb, pA, out);
}